// round 17
// baseline (speedup 1.0000x reference)
#include <cuda_runtime.h>
#include <math.h>

#define NB     8
#define D_IN   514
#define T_IN   4000
#define T_OUT  3999
#define NCOL   32                // FFT columns per block
#define NOUT   29                // output columns per block (3 halo)
#define ST     33                // plane row stride (in float2), odd
#define NTHR   512

// Slot permutation left by the in-place DFT16: F[k] lives at slot sigma(k).
#define SIGMA(k) ((((k) & 3) << 2) | ((k) >> 2))
// Store-back row map: z[q] (q = lk + 16*k2) lives at row 16*lk + ((k2+lk)&15).
#define ZROW(q) ((((q) & 15) << 4) | ((((q) >> 4) + (q)) & 15))

// dynamic smem: A[256*ST] float2 | tw[128] float2 | tw2[256] float2
#define SM_A    0
#define SM_TW   (256 * ST)
#define SM_TW2  (256 * ST + 128)
#define SM_F2   (256 * ST + 128 + 256)
#define SMEM_BYTES (SM_F2 * 8)

// ---------------------------------------------------------------------------
// 16-pt complex DFT, e^{+} kernel, IN PLACE. Output at slot SIGMA(k).
// ---------------------------------------------------------------------------
__device__ __forceinline__ void dft16_ip(float* xr, float* xi) {
    const float W16R[16] = { 1.0f,  0.923879533f,  0.707106781f,  0.382683432f,
                             0.0f, -0.382683432f, -0.707106781f, -0.923879533f,
                            -1.0f, -0.923879533f, -0.707106781f, -0.382683432f,
                             0.0f,  0.382683432f,  0.707106781f,  0.923879533f };
    const float W16I[16] = { 0.0f,  0.382683432f,  0.707106781f,  0.923879533f,
                             1.0f,  0.923879533f,  0.707106781f,  0.382683432f,
                             0.0f, -0.382683432f, -0.707106781f, -0.923879533f,
                            -1.0f, -0.923879533f, -0.707106781f, -0.382683432f };
#pragma unroll
    for (int b = 0; b < 4; b++) {
        float a0r = xr[b],      a0i = xi[b];
        float a1r = xr[b + 4],  a1i = xi[b + 4];
        float a2r = xr[b + 8],  a2i = xi[b + 8];
        float a3r = xr[b + 12], a3i = xi[b + 12];
        float t0r = a0r + a2r, t0i = a0i + a2i;
        float t1r = a0r - a2r, t1i = a0i - a2i;
        float t2r = a1r + a3r, t2i = a1i + a3i;
        float t3r = a1r - a3r, t3i = a1i - a3i;
        float p0r = t0r + t2r, p0i = t0i + t2i;
        float p1r = t1r - t3i, p1i = t1i + t3r;   // + i*t3
        float p2r = t0r - t2r, p2i = t0i - t2i;
        float p3r = t1r + t3i, p3i = t1i - t3r;   // - i*t3
        xr[b] = p0r;  xi[b] = p0i;
#pragma unroll
        for (int jj = 1; jj < 4; jj++) {
            float pr = (jj == 1) ? p1r : (jj == 2) ? p2r : p3r;
            float pi = (jj == 1) ? p1i : (jj == 2) ? p2i : p3i;
            float wr = W16R[(b * jj) & 15], wi = W16I[(b * jj) & 15];
            xr[b + 4 * jj] = pr * wr - pi * wi;
            xi[b + 4 * jj] = pr * wi + pi * wr;
        }
    }
#pragma unroll
    for (int jj = 0; jj < 4; jj++) {
        float b0r = xr[4 * jj],     b0i = xi[4 * jj];
        float b1r = xr[4 * jj + 1], b1i = xi[4 * jj + 1];
        float b2r = xr[4 * jj + 2], b2i = xi[4 * jj + 2];
        float b3r = xr[4 * jj + 3], b3i = xi[4 * jj + 3];
        float t0r = b0r + b2r, t0i = b0i + b2i;
        float t1r = b0r - b2r, t1i = b0i - b2i;
        float t2r = b1r + b3r, t2i = b1i + b3i;
        float t3r = b1r - b3r, t3i = b1i - b3i;
        xr[4 * jj]     = t0r + t2r;  xi[4 * jj]     = t0i + t2i;
        xr[4 * jj + 1] = t1r - t3i;  xi[4 * jj + 1] = t1i + t3r;
        xr[4 * jj + 2] = t0r - t2r;  xi[4 * jj + 2] = t0i - t2i;
        xr[4 * jj + 3] = t1r + t3i;  xi[4 * jj + 3] = t1i - t3r;
    }
}

// ---------------------------------------------------------------------------
// Fused: conj-sym pack -> 256-pt register FFT (16x16 CT) -> windowed OLA.
// 512 threads, 32 FFT cols (3 halo), 29 outputs per block. 4 barriers.
// Epilogue: j-pair vectorized (one float2 cell serves both parities).
// ---------------------------------------------------------------------------
__global__ __launch_bounds__(NTHR, 2) void fused_kernel(const float* __restrict__ in,
                                                        const float* __restrict__ win,
                                                        float* __restrict__ out) {
    extern __shared__ float2 sm[];
    float2* A   = sm + SM_A;      // row stride ST (float2)
    float2* tw  = sm + SM_TW;     // e^{+pi i k/256}
    float2* tw2 = sm + SM_TW2;    // e^{+2pi i m/256}

    const int tid = threadIdx.x;
    const int c   = tid & 31;
    const int lk  = tid >> 5;                 // 0..15
    const int b   = blockIdx.y;
    const int t0  = blockIdx.x * NOUT;
    const float* base = in + (size_t)b * D_IN * T_IN + t0 - 3;

    if (tid < 128)
        tw[tid] = make_float2(cospif(tid / 256.0f), sinpif(tid / 256.0f));
    else if (tid < 384) {
        int m = tid - 128;
        tw2[m] = make_float2(cospif(m / 128.0f), sinpif(m / 128.0f));
    }
    __syncthreads();                                       // [1]

    // ---- Build G[k] (zero out-of-range columns) ----
#pragma unroll
    for (int it = 0; it < 9; it++) {
        int idx = tid + it * NTHR;
        if (idx >= 129 * NCOL) break;
        int kp = idx >> 5;
        int cc = idx & 31;
        int gt = t0 - 3 + cc;
        bool v = (gt >= 0) && (gt < T_IN);
        if (kp == 0) {
            float r0 = v ? base[cc] : 0.0f;
            A[cc] = make_float2(r0, r0);
        } else if (kp == 128) {
            float r = v ? base[(size_t)128 * T_IN + cc] : 0.0f;
            float m = v ? base[(size_t)385 * T_IN + cc] : 0.0f;   // 257+128
            A[128 * ST + cc] = make_float2(2.0f * r, 2.0f * m);
        } else {
            float rk = 0.0f, mk = 0.0f, rp = 0.0f, mp = 0.0f;
            if (v) {
                rk = base[(size_t)kp * T_IN + cc];
                mk = base[(size_t)(257 + kp) * T_IN + cc];
                rp = base[(size_t)(256 - kp) * T_IN + cc];
                mp = base[(size_t)(513 - kp) * T_IN + cc];
            }
            float Er = rk + rp, Ei = mp - mk;
            float Dr = rk - rp, Di = -(mk + mp);
            float2 w = tw[kp];
            float Or = Dr * w.x - Di * w.y;
            float Oi = Dr * w.y + Di * w.x;
            A[kp * ST + cc]         = make_float2(Er - Oi, Ei + Or);
            A[(256 - kp) * ST + cc] = make_float2(Er + Oi, Or - Ei);
        }
    }
    __syncthreads();                                       // [2]

    float xr[16], xi[16];

    // ---- Phase 1: thread (c, n2=lk): X[a] = G[16a+lk] ----
#pragma unroll
    for (int a = 0; a < 16; a++) {
        float2 v = A[(16 * a + lk) * ST + c];
        xr[a] = v.x;
        xi[a] = v.y;
    }
    dft16_ip(xr, xi);     // F1[k1] at slot SIGMA(k1)

    // ---- Mid twiddle: F1[k1] *= W256^{+lk*k1} ----
#pragma unroll
    for (int k1 = 1; k1 < 16; k1++) {
        int s = SIGMA(k1);
        float2 w = tw2[lk * k1];
        float fr = xr[s], fi = xi[s];
        xr[s] = fr * w.x - fi * w.y;
        xi[s] = fr * w.y + fi * w.x;
    }

    // ---- Exchange: same thread-private row set as phase-1 reads: no barrier ----
#pragma unroll
    for (int k1 = 0; k1 < 16; k1++) {
        int s = SIGMA(k1);
        A[(16 * k1 + lk) * ST + c] = make_float2(xr[s], xi[s]);
    }
    __syncthreads();                                       // [3]

    // ---- Phase 2: thread (c, k1=lk): Y[n2] = H[n2][k1] ----
#pragma unroll
    for (int n2 = 0; n2 < 16; n2++) {
        float2 v = A[(16 * lk + n2) * ST + c];
        xr[n2] = v.x;
        xi[n2] = v.y;
    }
    dft16_ip(xr, xi);     // F2[k2] at slot SIGMA(k2)

    // ---- Store z[q] at row ZROW(q): inside own phase-2 row set, no barrier ----
#pragma unroll
    for (int k2 = 0; k2 < 16; k2++) {
        int s = SIGMA(k2);
        A[(16 * lk + ((k2 + lk) & 15)) * ST + c] = make_float2(xr[s], xi[s]);
    }
    __syncthreads();                                       // [4]

    // ---- Epilogue, j-pair vectorized.
    //  j0 = 2jp (comp .y), j1 = 2jp+1 (comp .x); both share rows
    //  q1 = 255-jp (S1 family) and q2 = 127-jp (S2 family).
    //  out[dt][j]  = w1*S1[dt+3] + w2*S2[dt+2] + w3*S1[dt+1] + w4*S2[dt]. ----
    {
        const int jp  = tid & 127;
        const int qh  = tid >> 7;                 // dt quarter 0..3
        const int dt0 = (qh == 0) ? 0 : (1 + 7 * qh);   // 0,8,15,22
        const int nq  = (qh == 0) ? 8 : 7;
        const int j0  = 2 * jp;
        const int j1  = j0 + 1;

        const float w1a = 256.0f * __ldg(&win[1023 - j0]);
        const float w2a = 256.0f * __ldg(&win[767 - j0]);
        const float w3a = 256.0f * __ldg(&win[511 - j0]);
        const float w4a = 256.0f * __ldg(&win[255 - j0]);
        const float w1b = 256.0f * __ldg(&win[1023 - j1]);
        const float w2b = 256.0f * __ldg(&win[767 - j1]);
        const float w3b = 256.0f * __ldg(&win[511 - j1]);
        const float w4b = 256.0f * __ldg(&win[255 - j1]);

        const float2* r1 = A + ZROW(255 - jp) * ST;
        const float2* r2 = A + ZROW(127 - jp) * ST;
        float2 p1a = r1[dt0 + 1];
        float2 p1b = r1[dt0 + 2];
        float2 p2a = r2[dt0 + 0];
        float2 p2b = r2[dt0 + 1];

        float2* ob = reinterpret_cast<float2*>(out + ((size_t)b * T_OUT + t0) * 256) + jp;
#pragma unroll
        for (int q = 0; q < 8; q++) {
            if (q >= nq) break;
            int dt = dt0 + q;
            if (t0 + dt >= T_OUT) break;
            float2 n1v = r1[dt + 3];
            float2 n2v = r2[dt + 2];
            float vj0 = w1a * n1v.y + w2a * n2v.y + w3a * p1a.y + w4a * p2a.y;
            float vj1 = w1b * n1v.x + w2b * n2v.x + w3b * p1a.x + w4b * p2a.x;
            ob[(size_t)dt * 128] = make_float2(vj0, vj1);
            p1a = p1b; p1b = n1v;
            p2a = p2b; p2b = n2v;
        }
    }
}

// ---------------------------------------------------------------------------
extern "C" void kernel_launch(void* const* d_in, const int* in_sizes, int n_in,
                              void* d_out, int out_size) {
    const float* in  = (const float*)d_in[0];   // (8, 514, 4000) f32
    const float* win = (const float*)d_in[1];   // (1024,) f32
    float* out = (float*)d_out;                 // (8, 3999*256) f32

    cudaFuncSetAttribute(fused_kernel,
                         cudaFuncAttributeMaxDynamicSharedMemorySize, SMEM_BYTES);

    dim3 g((T_OUT + NOUT - 1) / NOUT, NB);      // (138, 8)
    fused_kernel<<<g, NTHR, SMEM_BYTES>>>(in, win, out);
}